// round 12
// baseline (speedup 1.0000x reference)
#include <cuda_runtime.h>
#include <cstdint>

// LFQ quantizer — sparse factorized softmax, ONE kernel, ONE 8-CTA cluster,
// ALL intermediates in (distributed) shared memory. No __device__ globals,
// no __threadfence, no L2 round trips except the unavoidable x-in / q-out.
// N = 8192 samples, D = 14, K = 16384, T = 0.01.
//
// softmax factorizes: p_j = prod_d sigmoid(400 x_d c_jd).
// u_d = e^{-400|x_d|} > 1e-4 only for |x_d| < 0.023 -> each sample's mass
// lives on ~1.3 codes: enumerate subsets of the soft-dim mask.
// sample_entropy = sum_d binary_entropy(sigmoid(400 x_d)) (factorized).
//
// Code j's accumulator lives in CTA (j>>11)'s smem (2048 codes per CTA).
// Scatter = mapa + red.shared::cluster.add.f32 (fire-and-forget DSMEM atomic).
// cluster.sync guarantees DSMEM visibility -> no fences needed.
// Graph-replay safe by construction: all state is smem, zeroed on entry.

#define DIMS 14
#define NCODES 16384
#define NB 8
#define BTH 1024
#define EPB (BTH * DIMS)       // 14336 floats per block
#define E4PB (EPB / 4)         // 3584 float4 per block
#define CPB (NCODES / NB)      // 2048 codes owned per CTA
#define UTH 1e-4f

// shared layout (float words): slots[16] | M[CPB] | us[EPB]
#define OFF_SLOTS 0            // [0]=commit, [1]=sampH, [2]=avgH (CTA0 only)
#define OFF_M 16
#define OFF_US (OFF_M + CPB)
#define SMEM_WORDS (OFF_US + EPB)
#define SMEM_BYTES (SMEM_WORDS * 4)   // 16+2048+14336 words = 65600 B

#define CLUSTER_SYNC() do { \
    asm volatile("barrier.cluster.arrive.aligned;" ::: "memory"); \
    asm volatile("barrier.cluster.wait.aligned;" ::: "memory"); \
} while (0)

__device__ __forceinline__ uint32_t smem_u32(const void* p) {
    uint32_t a;
    asm("{ .reg .u64 t; cvta.to.shared.u64 t, %1; cvt.u32.u64 %0, t; }"
        : "=r"(a) : "l"(p));
    return a;
}

// atomicAdd into the cluster-peer CTA `rank`'s smem at the same local offset
__device__ __forceinline__ void red_remote(uint32_t laddr, uint32_t rank, float v) {
    asm volatile(
        "{ .reg .b32 r; mapa.shared::cluster.u32 r, %0, %1;\n\t"
        "red.shared::cluster.add.f32 [r], %2; }"
        :: "r"(laddr), "r"(rank), "f"(v) : "memory");
}

__global__ void __launch_bounds__(BTH, 1) __cluster_dims__(NB, 1, 1)
lfq_fused(const float* __restrict__ x, float* __restrict__ out,
          int qn, int out_size, float inv_n) {
    extern __shared__ float sm[];
    float* slots = sm + OFF_SLOTS;
    float* M     = sm + OFF_M;
    unsigned* us = (unsigned*)(sm + OFF_US);   // bit31=sign, rest = u bits

    __shared__ float w1[32], w2[32];

    const int tid = threadIdx.x;
    const int lane = tid & 31, wid = tid >> 5;
    const int bid = blockIdx.x;                // == cluster rank (single cluster)
    const float4* x4 = (const float4*)x + bid * E4PB;
    float4* o4 = (float4*)out + bid * E4PB;

    const uint32_t M_addr    = smem_u32(M);
    const uint32_t slot_addr = smem_u32(slots);

    // zero own M slice + slots (state is per-launch; replay-safe)
    for (int i = tid; i < OFF_US; i += BTH) sm[i] = 0.f;

    // ========== phase A: elementwise, coalesced float4 ==========
    float commit = 0.f, h = 0.f;
    #pragma unroll
    for (int k = 0; k < 4; ++k) {
        int i = tid + k * BTH;
        if (i < E4PB) {
            float4 xv = x4[i];
            float vx[4] = {xv.x, xv.y, xv.z, xv.w};
            float qq[4];
            #pragma unroll
            for (int j = 0; j < 4; ++j) {
                float v = vx[j];
                bool pos = (v > 0.f);
                float qz = pos ? 1.f : -1.f;
                qq[j] = qz;
                float dq = v - qz;
                commit += dq * dq;
                float t = fabsf(400.f * v);
                float u = __expf(-t);                    // flip ratio e^{-|z|}
                float inv = 1.f / (1.f + u);
                h += (u > 1e-4f) ? (__logf(1.f + u) + t * u * inv)
                                 : u * (1.f + t);        // 1st order, err ~ u^2
                us[4 * i + j] = __float_as_uint(u) | (pos ? 0x80000000u : 0u);
            }
            float4 q; q.x = qq[0]; q.y = qq[1]; q.z = qq[2]; q.w = qq[3];
            o4[i] = q;                                   // coalesced STG.128
        }
    }
    __syncthreads();

    // ========== sync #1: every CTA's M slice is zeroed ==========
    CLUSTER_SYNC();

    // ========== phase B: per-sample sparse scatter into DSMEM ==========
    {
        const unsigned* up = &us[tid * DIMS];
        float pr = 1.f;                                  // prod (1 + u_d)
        int j_main = 0;
        unsigned soft = 0;
        #pragma unroll
        for (int d = 0; d < DIMS; ++d) {
            unsigned w = up[d];
            float u = __uint_as_float(w & 0x7fffffffu);
            if (w >> 31) j_main |= (1 << d);
            pr *= (1.f + u);
            if (u > UTH) soft |= (1u << d);
        }
        float p_main = __fdividef(1.f, pr);              // one rcp per sample
        unsigned m = 0;
        do {                                             // subsets of `soft`
            float p = p_main;
            unsigned r = m;
            while (r) {
                int d = __ffs(r) - 1;
                p *= __uint_as_float(up[d] & 0x7fffffffu);
                r &= r - 1;
            }
            unsigned j = (unsigned)j_main ^ m;
            red_remote(M_addr + (j & (CPB - 1u)) * 4u, j >> 11, p);
            m = (m - soft) & soft;
        } while (m);
    }

    // block-reduce commit & sample-entropy -> DSMEM slots on CTA 0
    #pragma unroll
    for (int off = 16; off; off >>= 1) {
        commit += __shfl_down_sync(0xffffffffu, commit, off);
        h      += __shfl_down_sync(0xffffffffu, h, off);
    }
    if (lane == 0) { w1[wid] = commit; w2[wid] = h; }
    __syncthreads();
    if (wid == 0) {
        float cs = w1[lane], hs = w2[lane];
        #pragma unroll
        for (int off = 16; off; off >>= 1) {
            cs += __shfl_down_sync(0xffffffffu, cs, off);
            hs += __shfl_down_sync(0xffffffffu, hs, off);
        }
        if (lane == 0) {
            red_remote(slot_addr + 0u, 0u, cs);
            red_remote(slot_addr + 4u, 0u, hs);
        }
    }

    // ========== sync #2: all scatters visible (cluster.sync orders DSMEM) ==========
    CLUSTER_SYNC();

    // ========== phase C: entropy over own M slice (pure LDS) ==========
    float ea = 0.f;
    #pragma unroll
    for (int k = 0; k < CPB / BTH; ++k) {                // 2 iters
        float v = M[k * BTH + tid];
        float mm = v * inv_n;
        ea -= mm * __logf(mm + 1e-5f);                   // mm==0 -> exactly 0
    }
    #pragma unroll
    for (int off = 16; off; off >>= 1)
        ea += __shfl_down_sync(0xffffffffu, ea, off);
    if (lane == 0) w1[wid] = ea;
    __syncthreads();
    if (tid == 0) {
        float es = 0.f;
        #pragma unroll
        for (int w = 0; w < 32; ++w) es += w1[w];
        red_remote(slot_addr + 8u, 0u, es);
    }

    // ========== sync #3, then rank 0 writes the 4 scalars ==========
    CLUSTER_SYNC();

    if (bid == 0 && tid == 0 && out_size >= qn + 4) {
        float cs = slots[0], hs = slots[1], es = slots[2];
        float samp = hs * inv_n;
        float cm = cs * inv_n * (1.f / (float)DIMS);
        out[qn + 0] = samp - es;                         // entropy_aux_loss
        out[qn + 1] = samp;                              // sample_entropy
        out[qn + 2] = es;                                // avg_entropy
        out[qn + 3] = cm;                                // commit_loss
    }
}

extern "C" void kernel_launch(void* const* d_in, const int* in_sizes, int n_in,
                              void* d_out, int out_size) {
    const float* x = (const float*)d_in[0];
    float* out = (float*)d_out;
    int qn = in_sizes[0];                   // 8*1024*14 = 114688
    float inv_n = 1.f / (float)(qn / DIMS); // 1/8192

    static bool attr_set = false;           // capture-time host attribute only
    if (!attr_set) {
        cudaFuncSetAttribute(lfq_fused, cudaFuncAttributeMaxDynamicSharedMemorySize,
                             SMEM_BYTES);
        attr_set = true;
    }
    lfq_fused<<<NB, BTH, SMEM_BYTES>>>(x, out, qn, out_size, inv_n);
}

// round 15
// speedup vs baseline: 1.1912x; 1.1912x over previous
#include <cuda_runtime.h>
#include <cstdint>

// LFQ quantizer — sparse factorized softmax, ONE kernel, ONE 8-CTA cluster,
// bulk-DMA (TMA) I/O. N = 8192 samples, D = 14, K = 16384, T = 0.01.
//
// softmax factorizes: p_j = prod_d sigmoid(400 x_d c_jd).
// u_d = e^{-400|x_d|} > 1e-4 only for |x_d| < 0.023 -> each sample's mass
// lives on ~1.3 codes: enumerate subsets of the soft-dim mask.
// sample_entropy = sum_d binary_entropy(sigmoid(400 x_d)) (factorized).
//
// The ~18.5us floor of rounds 9-12 was latency-limited per-thread LDG/STG:
// 8 CTAs can't keep enough bytes in flight (~4-8KB/SM vs 530ns DRAM latency).
// Fix: one cp.async.bulk 56KB load per CTA (TMA engine, deep HW queue),
// compute q in-place in smem, one bulk-group store that completes in the
// background overlapped with scatter + barriers; drained at kernel end.
//
// Graph-replay safe: g_M re-zeroed in phase D, mbarrier re-inited per launch,
// no persistent counters.

#define DIMS 14
#define NCODES 16384
#define NB 8
#define BTH 1024
#define EPB (BTH * DIMS)       // 14336 floats per CTA
#define E4PB (EPB / 4)         // 3584 float4 per CTA
#define CPB (NCODES / NB)      // 2048 codes per CTA in phase D
#define UTH 1e-4f
#define TILE_BYTES (EPB * 4)   // 57344 B
#define SMEM_BYTES (2 * TILE_BYTES)   // x/q tile + us tile

__device__ float g_M[NCODES];                  // per-code prob sums (zeroed each run)
__device__ float g_cP[NB], g_hP[NB], g_eP[NB]; // per-block partial slots

#define CLUSTER_SYNC() do { \
    asm volatile("barrier.cluster.arrive.aligned;" ::: "memory"); \
    asm volatile("barrier.cluster.wait.aligned;" ::: "memory"); \
} while (0)

__device__ __forceinline__ uint32_t smem_u32(const void* p) {
    uint32_t a;
    asm("{ .reg .u64 t; cvta.to.shared.u64 t, %1; cvt.u32.u64 %0, t; }"
        : "=r"(a) : "l"(p));
    return a;
}

__device__ __forceinline__ void mbar_wait(uint32_t mbar, uint32_t parity) {
    asm volatile(
        "{\n\t.reg .pred P;\n\t"
        "W_%=: mbarrier.try_wait.parity.shared.b64 P, [%0], %1;\n\t"
        "@P bra.uni D_%=;\n\t"
        "bra.uni W_%=;\n\t"
        "D_%=:\n\t}"
        :: "r"(mbar), "r"(parity) : "memory");
}

__global__ void __launch_bounds__(BTH, 1) __cluster_dims__(NB, 1, 1)
lfq_fused(const float* __restrict__ x, float* __restrict__ out,
          int qn, int out_size, float inv_n) {
    extern __shared__ float sm[];
    float* xs = sm;                              // [EPB] x in, q out (in place)
    unsigned* us = (unsigned*)(sm + EPB);        // [EPB] bit31=sign, rest=u bits
    __shared__ float w1[32], w2[32];
    __shared__ alignas(8) unsigned long long mbar;

    const int tid = threadIdx.x;
    const int lane = tid & 31, wid = tid >> 5;
    const int bid = blockIdx.x;                  // == cluster rank
    const float* xg = x + bid * EPB;
    float* og = out + bid * EPB;
    const uint32_t xs_addr = smem_u32(xs);
    const uint32_t mbar_addr = smem_u32(&mbar);

    // ---- bulk DMA: global x slice -> smem (one 56KB op) ----
    if (tid == 0) {
        asm volatile("mbarrier.init.shared.b64 [%0], %1;"
                     :: "r"(mbar_addr), "r"(1u) : "memory");
    }
    __syncthreads();
    if (tid == 0) {
        asm volatile("mbarrier.arrive.expect_tx.shared.b64 _, [%0], %1;"
                     :: "r"(mbar_addr), "r"((unsigned)TILE_BYTES) : "memory");
        asm volatile(
            "cp.async.bulk.shared::cta.global.mbarrier::complete_tx::bytes "
            "[%0], [%1], %2, [%3];"
            :: "r"(xs_addr), "l"(xg), "r"((unsigned)TILE_BYTES), "r"(mbar_addr)
            : "memory");
    }
    mbar_wait(mbar_addr, 0);

    // ========== phase A: elementwise from smem, q written back in place ==========
    float commit = 0.f, h = 0.f;
    #pragma unroll
    for (int k = 0; k < 4; ++k) {
        int i = tid + k * BTH;
        if (i < E4PB) {
            float4 xv = ((const float4*)xs)[i];
            float vx[4] = {xv.x, xv.y, xv.z, xv.w};
            float qq[4];
            #pragma unroll
            for (int j = 0; j < 4; ++j) {
                float v = vx[j];
                bool pos = (v > 0.f);
                float qz = pos ? 1.f : -1.f;
                qq[j] = qz;
                float dq = v - qz;
                commit += dq * dq;
                float t = fabsf(400.f * v);
                float u = __expf(-t);                    // flip ratio e^{-|z|}
                float inv = 1.f / (1.f + u);
                h += (u > 1e-4f) ? (__logf(1.f + u) + t * u * inv)
                                 : u * (1.f + t);        // 1st order, err ~ u^2
                us[4 * i + j] = __float_as_uint(u) | (pos ? 0x80000000u : 0u);
            }
            float4 q; q.x = qq[0]; q.y = qq[1]; q.z = qq[2]; q.w = qq[3];
            ((float4*)xs)[i] = q;                        // in-place q tile
        }
    }
    __syncthreads();

    // ---- bulk DMA: smem q tile -> global (background; drained at end) ----
    if (tid == 0) {
        asm volatile("fence.proxy.async.shared::cta;" ::: "memory");
        asm volatile("cp.async.bulk.global.shared::cta.bulk_group [%0], [%1], %2;"
                     :: "l"(og), "r"(xs_addr), "r"((unsigned)TILE_BYTES) : "memory");
        asm volatile("cp.async.bulk.commit_group;" ::: "memory");
    }

    // ========== phase B: per-sample sparse scatter (1 thread/sample) ==========
    {
        const unsigned* up = &us[tid * DIMS];
        float pr = 1.f;                                  // prod (1 + u_d)
        int j_main = 0;
        unsigned soft = 0;
        #pragma unroll
        for (int d = 0; d < DIMS; ++d) {
            unsigned w = up[d];
            float u = __uint_as_float(w & 0x7fffffffu);
            if (w >> 31) j_main |= (1 << d);
            pr *= (1.f + u);
            if (u > UTH) soft |= (1u << d);
        }
        float p_main = __fdividef(1.f, pr);              // one rcp per sample
        unsigned m = 0;
        do {                                             // subsets of `soft`
            float p = p_main;
            unsigned r = m;
            while (r) {
                int d = __ffs(r) - 1;
                p *= __uint_as_float(up[d] & 0x7fffffffu);
                r &= r - 1;
            }
            atomicAdd(&g_M[j_main ^ (int)m], p);         // fire-and-forget REDG
            m = (m - soft) & soft;
        } while (m);
    }

    // block-reduce commit & sample-entropy (32 warps)
    #pragma unroll
    for (int off = 16; off; off >>= 1) {
        commit += __shfl_down_sync(0xffffffffu, commit, off);
        h      += __shfl_down_sync(0xffffffffu, h, off);
    }
    if (lane == 0) { w1[wid] = commit; w2[wid] = h; }
    __syncthreads();
    if (wid == 0) {
        float cs = w1[lane], hs = w2[lane];
        #pragma unroll
        for (int off = 16; off; off >>= 1) {
            cs += __shfl_down_sync(0xffffffffu, cs, off);
            hs += __shfl_down_sync(0xffffffffu, hs, off);
        }
        if (lane == 0) { g_cP[bid] = cs; g_hP[bid] = hs; }
    }

    // ========== grid barrier #1 ==========
    __threadfence();                   // publish g_M atomics + partial STGs
    CLUSTER_SYNC();

    // ========== phase D: distributed entropy over avg_probs + re-zero ==========
    float ea = 0.f;
    const int base = bid * CPB;
    #pragma unroll
    for (int k = 0; k < CPB / BTH; ++k) {                // 2 iters, coalesced
        int c = base + k * BTH + tid;
        float v = __ldcg(&g_M[c]);
        g_M[c] = 0.f;                                    // reset for next replay
        float mm = v * inv_n;
        ea -= mm * __logf(mm + 1e-5f);                   // mm==0 -> exactly 0
    }
    #pragma unroll
    for (int off = 16; off; off >>= 1)
        ea += __shfl_down_sync(0xffffffffu, ea, off);
    if (lane == 0) w1[wid] = ea;
    __syncthreads();
    if (tid == 0) {
        float es = 0.f;
        #pragma unroll
        for (int w = 0; w < 32; ++w) es += w1[w];
        g_eP[bid] = es;
    }

    // ========== grid barrier #2, then rank 0 finalizes ==========
    __threadfence();                   // publish g_eP
    CLUSTER_SYNC();

    if (bid == 0 && wid == 0) {
        float cs = (lane < NB) ? g_cP[lane] : 0.f;
        float hs = (lane < NB) ? g_hP[lane] : 0.f;
        float es = (lane < NB) ? g_eP[lane] : 0.f;
        #pragma unroll
        for (int off = 4; off; off >>= 1) {
            cs += __shfl_down_sync(0xffffffffu, cs, off);
            hs += __shfl_down_sync(0xffffffffu, hs, off);
            es += __shfl_down_sync(0xffffffffu, es, off);
        }
        if (lane == 0) {
            float samp = hs * inv_n;
            float cm = cs * inv_n * (1.f / (float)DIMS);
            if (out_size >= qn + 4) {
                out[qn + 0] = samp - es;                 // entropy_aux_loss
                out[qn + 1] = samp;                      // sample_entropy
                out[qn + 2] = es;                        // avg_entropy
                out[qn + 3] = cm;                        // commit_loss
            }
        }
    }

    // drain the background q-tile store before exit
    if (tid == 0)
        asm volatile("cp.async.bulk.wait_group %0;" :: "n"(0) : "memory");
}

extern "C" void kernel_launch(void* const* d_in, const int* in_sizes, int n_in,
                              void* d_out, int out_size) {
    const float* x = (const float*)d_in[0];
    float* out = (float*)d_out;
    int qn = in_sizes[0];                   // 8*1024*14 = 114688
    float inv_n = 1.f / (float)(qn / DIMS); // 1/8192

    static bool attr_set = false;           // capture-time host attribute only
    if (!attr_set) {
        cudaFuncSetAttribute(lfq_fused, cudaFuncAttributeMaxDynamicSharedMemorySize,
                             SMEM_BYTES);
        attr_set = true;
    }
    lfq_fused<<<NB, BTH, SMEM_BYTES>>>(x, out, qn, out_size, inv_n);
}

// round 16
// speedup vs baseline: 1.3159x; 1.1047x over previous
#include <cuda_runtime.h>

// LFQ quantizer — sparse factorized softmax, single kernel, 64 CTAs.
// N = 8192 samples, D = 14, K = 16384, T = 0.01.
//
// Model (round 15 rebuild): all prior variants were PHASE-A ISSUE/LATENCY
// bound (~190K inst on 8 SMs, or 2-warp/SMSP latency on 32 SMs). This version
// cuts phase A to ~5 inst/elem and runs it on 64 SMs with 4 warps/SMSP:
//   q        = sign-copy bit trick (1 LOP3)
//   commit   = sum(x^2) - 2 sum(|x|) + count   (q = sign(x) identity)
//   entropy  = soft elements only (|x| < 0.035, ~2.8%); hard-dim
//              contribution < 5e-7 rel (validated in round 11)
//   scatter  = subsets of per-sample soft bitmask (~1.3 codes/sample);
//              67% of samples have empty mask -> single REDG of 1.0
// Sync: counter arrive + nanosleep poll (round-9 proven), distributed
// phase D (256 codes/CTA), ticket finalize. Graph-replay safe: g_M re-zeroed
// in phase D, g_bar/g_ticket reset by the last block.

#define DIMS 14
#define NCODES 16384
#define NB 64
#define BTH 512
#define SPB 128                 // samples per CTA
#define EPB (SPB * DIMS)        // 1792 elements per CTA
#define F4PB (EPB / 4)          // 448 float4 per CTA
#define CPB (NCODES / NB)       // 256 codes per CTA in phase D
#define QCAP 256
#define SOFTX 0.035f            // |x| < 14/400
#define UTH 1e-4f

__device__ float g_M[NCODES];                  // per-code prob sums (zeroed each run)
__device__ float g_cP[NB], g_hP[NB], g_eP[NB]; // per-block partial slots
__device__ unsigned g_bar, g_ticket;

__global__ __launch_bounds__(BTH) void lfq_fused(const float* __restrict__ x,
                                                 float* __restrict__ out,
                                                 int qn, int out_size,
                                                 float inv_n) {
    __shared__ float xs[EPB];        // raw x tile (sign source for phase C)
    __shared__ float us[EPB];        // u values, written ONLY at soft positions
    __shared__ unsigned smask[SPB];  // per-sample soft-dim bitmask
    __shared__ unsigned qi[QCAP];
    __shared__ float qt[QCAP];
    __shared__ float w1[16], w2[16];
    __shared__ int s_qn, s_last;

    const int tid = threadIdx.x;
    const int lane = tid & 31, wid = tid >> 5;
    const int bid = blockIdx.x;

    if (tid < SPB) smask[tid] = 0u;
    if (tid == 0) s_qn = 0;
    __syncthreads();

    // ========== phase A: elementwise, ~5 inst/elem ==========
    float s1 = 0.f, s2 = 0.f, h = 0.f;
    if (tid < F4PB) {
        const float4* xg4 = (const float4*)x + bid * F4PB;
        float4* og4 = (float4*)out + bid * F4PB;
        float4 xv = xg4[tid];
        float v[4] = {xv.x, xv.y, xv.z, xv.w};
        unsigned qb[4];
        #pragma unroll
        for (int j = 0; j < 4; ++j) {
            float f = v[j];
            unsigned ub = __float_as_uint(f);
            qb[j] = (ub & 0x80000000u) | 0x3F800000u;    // q = +-1 sign copy
            s2 += f * f;
            float a = fabsf(f);
            s1 += a;
            if (a < SOFTX) {                             // ~2.8% of elements
                int e = 4 * tid + j;
                float t = 400.f * a;
                int slot = atomicAdd(&s_qn, 1);
                if (slot < QCAP) { qi[slot] = e; qt[slot] = t; }
                else {                                   // overflow: inline
                    float u = __expf(-t);
                    us[e] = u;
                    unsigned s = (unsigned)e / 14u;
                    atomicOr(&smask[s], 1u << ((unsigned)e - 14u * s));
                    h += __logf(1.f + u) + t * u * __fdividef(1.f, 1.f + u);
                }
            }
        }
        ((float4*)xs)[tid] = xv;                         // keep raw x for phase C
        float4 q;
        q.x = __uint_as_float(qb[0]); q.y = __uint_as_float(qb[1]);
        q.z = __uint_as_float(qb[2]); q.w = __uint_as_float(qb[3]);
        og4[tid] = q;                                    // coalesced STG.128
    }
    __syncthreads();

    // ========== phase B: transcendentals on the ~50-entry queue ==========
    {
        int qcnt = s_qn < QCAP ? s_qn : QCAP;
        for (int i = tid; i < qcnt; i += BTH) {
            float t = qt[i];
            unsigned e = qi[i];
            float u = __expf(-t);
            us[e] = u;
            unsigned s = e / 14u, d = e - 14u * s;
            atomicOr(&smask[s], 1u << d);
            h += __logf(1.f + u) + t * u * __fdividef(1.f, 1.f + u);
        }
    }
    __syncthreads();

    // ========== phase C: per-sample scatter (threads 0..127) ==========
    if (tid < SPB) {
        unsigned j = 0;
        const unsigned* xw = (const unsigned*)(xs + tid * DIMS);
        #pragma unroll
        for (int d = 0; d < DIMS; ++d)
            j |= (((~xw[d]) >> 31) & 1u) << d;           // bit=1 iff x>=0
        unsigned mask = smask[tid];
        if (mask == 0u) {                                // ~67% of samples
            atomicAdd(&g_M[j], 1.f);                     // p = 1 (err < 1e-5)
        } else {
            const float* up = us + tid * DIMS;
            float pr = 1.f;
            unsigned soft = 0, mm = mask;
            while (mm) {
                int d = __ffs(mm) - 1; mm &= mm - 1;
                float u = up[d];
                pr *= (1.f + u);
                if (u > UTH) soft |= 1u << d;
            }
            float p_main = __fdividef(1.f, pr);
            unsigned m = 0;
            do {                                         // subsets of `soft`
                float p = p_main;
                unsigned r = m;
                while (r) { int d = __ffs(r) - 1; p *= up[d]; r &= r - 1; }
                atomicAdd(&g_M[j ^ m], p);
                m = (m - soft) & soft;
            } while (m);
        }
    }

    // block-reduce commit partial (s2 - 2*s1) and h (16 warps)
    float cp = s2 - 2.f * s1;
    #pragma unroll
    for (int off = 16; off; off >>= 1) {
        cp += __shfl_down_sync(0xffffffffu, cp, off);
        h  += __shfl_down_sync(0xffffffffu, h, off);
    }
    if (lane == 0) { w1[wid] = cp; w2[wid] = h; }

    // ========== grid barrier: arrive-first, store partials while waiting ==========
    __threadfence();                     // publish g_M REDGs
    __syncthreads();                     // w1/w2 ready
    if (tid == 0) {
        unsigned t = atomicAdd(&g_bar, 1u);
        float cs = 0.f, hs = 0.f;
        #pragma unroll
        for (int w = 0; w < 16; ++w) { cs += w1[w]; hs += w2[w]; }
        g_cP[bid] = cs;                  // plain STG (visibility via ticket fence)
        g_hP[bid] = hs;
        if (t != NB - 1)
            while (((volatile unsigned*)&g_bar)[0] < NB) __nanosleep(64);
    }
    __syncthreads();
    __threadfence();                     // acquire for g_M reads

    // ========== phase D: distributed entropy over avg_probs + re-zero ==========
    float ea = 0.f;
    if (tid < CPB) {                     // 256 codes per CTA, coalesced
        int c = bid * CPB + tid;
        float v = __ldcg(&g_M[c]);
        g_M[c] = 0.f;                    // reset for next graph replay
        float mm = v * inv_n;
        ea -= mm * __logf(mm + 1e-5f);   // mm==0 -> exactly 0
    }
    #pragma unroll
    for (int off = 16; off; off >>= 1)
        ea += __shfl_down_sync(0xffffffffu, ea, off);
    if (lane == 0) w1[wid] = ea;
    __syncthreads();

    if (tid == 0) {
        float es = 0.f;
        #pragma unroll
        for (int w = 0; w < 16; ++w) es += w1[w];
        g_eP[bid] = es;
        __threadfence();                 // release partials
        unsigned tk = atomicAdd(&g_ticket, 1u);
        s_last = (tk == NB - 1);
    }
    __syncthreads();
    if (!s_last) return;

    // ========== last block: sum 64 partial slots, write scalars, reset ==========
    __threadfence();                     // acquire all blocks' partial STGs
    if (wid == 0) {
        float cs = g_cP[lane] + g_cP[lane + 32];
        float hs = g_hP[lane] + g_hP[lane + 32];
        float es = g_eP[lane] + g_eP[lane + 32];
        #pragma unroll
        for (int off = 16; off; off >>= 1) {
            cs += __shfl_down_sync(0xffffffffu, cs, off);
            hs += __shfl_down_sync(0xffffffffu, hs, off);
            es += __shfl_down_sync(0xffffffffu, es, off);
        }
        if (lane == 0) {
            float samp = hs * inv_n;
            float cm = cs * inv_n * (1.f / (float)DIMS) + 1.f;
            if (out_size >= qn + 4) {
                out[qn + 0] = samp - es;                 // entropy_aux_loss
                out[qn + 1] = samp;                      // sample_entropy
                out[qn + 2] = es;                        // avg_entropy
                out[qn + 3] = cm;                        // commit_loss
            }
            g_bar = 0u;                                  // reset for next replay
            g_ticket = 0u;
        }
    }
}

extern "C" void kernel_launch(void* const* d_in, const int* in_sizes, int n_in,
                              void* d_out, int out_size) {
    const float* x = (const float*)d_in[0];
    float* out = (float*)d_out;
    int qn = in_sizes[0];                   // 8*1024*14 = 114688
    float inv_n = 1.f / (float)(qn / DIMS); // 1/8192

    lfq_fused<<<NB, BTH>>>(x, out, qn, out_size, inv_n);
}